// round 9
// baseline (speedup 1.0000x reference)
#include <cuda_runtime.h>

#define NN 100000
#define EE 200000
#define KK 16
#define FF 32
#define EPS 1e-5f
#define RPB 32      // rows per block (NN, EE both divide exactly)
#define SMEM_BYTES (RPB*160*4 + 80*16*16)   // zsh 20480 + WT4 20480 = 40960

typedef unsigned long long ull;

// Scratch (static device globals — no allocation).
__device__ float g_pmpd[NN * FF];   // segment_sum(y, dst) -> [N, F]
__device__ float g_stats[128];      // [xsum32 | xssq32 | ysum32 | yssq32]

#define FMA2(acc, a, b) asm("fma.rn.f32x2 %0, %1, %2, %0;" : "+l"(acc) : "l"(a), "l"(b))
#define FADD2(acc, a)   asm("add.rn.f32x2 %0, %0, %1;"     : "+l"(acc) : "l"(a))

// ---------------------------------------------------------------------------
__global__ void k_zero() {
    int i = blockIdx.x * 256 + threadIdx.x;      // [0, NN*8)
    ((float4*)g_pmpd)[i] = make_float4(0.f, 0.f, 0.f, 0.f);
    if (i < 128) g_stats[i] = 0.f;
}

// segment_sum: vectorized f32x2 global reductions (red.global.add.v2.f32).
__global__ void k_scatter(const float* __restrict__ y, const int* __restrict__ dst) {
    int i = blockIdx.x * 256 + threadIdx.x;   // [0, EE*16), exact
    int e = i >> 4, c = i & 15;               // 16 float2 chunks per 32-f row
    int d = __ldg(&dst[e]);                    // broadcast within half-warp
    float2 v = ((const float2*)y)[i];
    float* p = g_pmpd + d * FF + c * 2;
    asm volatile("{\n\t.reg .u64 q;\n\tcvta.to.global.u64 q, %0;\n\t"
                 "red.global.add.v2.f32 [q], {%1, %2};\n\t}"
                 :: "l"(p), "f"(v.x), "f"(v.y) : "memory");
}

// ---------------------------------------------------------------------------
// Fused per-row kernel. Row z = [v, deg*v, sum_t, sum_tt, p] (160 floats),
// out = z @ Wbig + bias ; relu cols [16:32) ; BN stats accumulation.
// 256 threads = 8 warps = 32 rows/block (5 blocks/SM -> 62.5% occ).
//   Gather: unchanged (R8) — LDG.64 two-neighbor-rows-per-instruction.
//   GEMM:   j-split warp pairs. Warps (2p, 2p+1) both cover rows 8p..8p+7;
//           warp's j-half = warp&1. Thread (g=lane>>4, o=lane&15) handles
//           4 rows (g selects row quad) x col-pair (o, o+16). W wavefronts
//           amortize over 8 rows (2x better than R8). Halves combined via a
//           partial buffer reused from the (dead) z smem region.
// ---------------------------------------------------------------------------
__global__ __launch_bounds__(256, 5) void k_main(
    const float* __restrict__ feat, const float* __restrict__ deg,
    const int* __restrict__ t, const int* __restrict__ tt,
    const float* __restrict__ psrc, const int* __restrict__ pidx,
    const float* __restrict__ w0, const float* __restrict__ w1,
    const float* __restrict__ w2, const float* __restrict__ w3,
    const float* __restrict__ w4,
    const float* __restrict__ b0, const float* __restrict__ b1,
    const float* __restrict__ b2, const float* __restrict__ b3,
    const float* __restrict__ b4,
    float* __restrict__ outp, int statoff)
{
    extern __shared__ char smem[];
    float* zsh = (float*)smem;                          // [RPB][160]
    float4* WT4s = (float4*)(smem + RPB * 160 * 4);     // [80][16] staging view
    const ulonglong2* WT4 = (const ulonglong2*)WT4s;    // read view
    __shared__ float biastot[32];
    __shared__ float s_sum[32], s_ssq[32];

    const float* pbase = psrc ? psrc : g_pmpd;
    float* stats = g_stats + statoff;

    int tid = threadIdx.x;
    // Stage packed weights: WT4[j2*16+o] = {W[2j2][o], W[2j2+1][o],
    //                                       W[2j2][o+16], W[2j2+1][o+16]}
    for (int i = tid; i < 80 * 16; i += 256) {
        int j2 = i >> 4, o = i & 15;
        int j = 2 * j2;
        const float* src = (j < 32) ? w0 : (j < 64) ? w1 : (j < 96) ? w2
                                   : (j < 128) ? w3 : w4;
        int jr = j & 31;          // j even -> j, j+1 share the same source block
        WT4s[i] = make_float4(src[jr * 32 + o],        src[(jr + 1) * 32 + o],
                              src[jr * 32 + o + 16],   src[(jr + 1) * 32 + o + 16]);
    }
    if (tid < 32) {
        biastot[tid] = b0[tid] + b1[tid] + b2[tid] + b3[tid] + b4[tid];
        s_sum[tid] = 0.f; s_ssq[tid] = 0.f;
    }
    __syncthreads();

    int lane = tid & 31, warp = tid >> 5;
    int row0 = blockIdx.x * RPB;
    int rbase = warp * 4;                 // 4 rows gathered per warp
    int l4 = lane & 15;
    int hb = lane >> 4;
    const ull* fb = (const ull*)feat;     // feat as float2 (8B) elements

    // ---- Gather phase (unchanged): 2 interleaved rows at a time ----
    #pragma unroll
    for (int s = 0; s < 4; s += 2) {
        int m0 = rbase + s, m1 = m0 + 1;
        int n0 = row0 + m0, n1 = row0 + m1;
        float xv0 = feat[n0 * FF + lane];
        float xv1 = feat[n1 * FF + lane];
        float dv0 = deg[n0] * xv0;
        float dv1 = deg[n1] * xv1;
        int ir0 = (lane < 16) ? t[n0 * KK + lane] : tt[n0 * KK + lane - 16];
        int ir1 = (lane < 16) ? t[n1 * KK + lane] : tt[n1 * KK + lane - 16];

        ull a00 = 0ull, a01 = 0ull, a10 = 0ull, a11 = 0ull;
        #pragma unroll
        for (int q = 0; q < 8; q++) {
            int sl = 2 * q + hb;
            int i00 = __shfl_sync(0xffffffffu, ir0, sl);
            int i01 = __shfl_sync(0xffffffffu, ir0, sl + 16);
            int i10 = __shfl_sync(0xffffffffu, ir1, sl);
            int i11 = __shfl_sync(0xffffffffu, ir1, sl + 16);
            ull v00 = fb[i00 * 16 + l4];
            ull v01 = fb[i01 * 16 + l4];
            ull v10 = fb[i10 * 16 + l4];
            ull v11 = fb[i11 * 16 + l4];
            FADD2(a00, v00);
            FADD2(a01, v01);
            FADD2(a10, v10);
            FADD2(a11, v11);
        }
        ull f00 = __shfl_xor_sync(0xffffffffu, a00, 16); FADD2(a00, f00);
        ull f01 = __shfl_xor_sync(0xffffffffu, a01, 16); FADD2(a01, f01);
        ull f10 = __shfl_xor_sync(0xffffffffu, a10, 16); FADD2(a10, f10);
        ull f11 = __shfl_xor_sync(0xffffffffu, a11, 16); FADD2(a11, f11);

        float pv0 = pidx ? pbase[pidx[n0] * FF + lane] : pbase[n0 * FF + lane];
        float pv1 = pidx ? pbase[pidx[n1] * FF + lane] : pbase[n1 * FF + lane];
        float* zr0 = zsh + m0 * 160;
        float* zr1 = zsh + m1 * 160;
        zr0[lane] = xv0;       zr1[lane] = xv1;
        zr0[32 + lane] = dv0;  zr1[32 + lane] = dv1;
        union Uc { ull u; float2 f; } c0, c1;
        c0.u = hb ? a01 : a00;
        c1.u = hb ? a11 : a10;
        int zo = (hb ? 96 : 64) + 2 * l4;
        *(float2*)(zr0 + zo) = c0.f;
        *(float2*)(zr1 + zo) = c1.f;
        zr0[128 + lane] = pv0; zr1[128 + lane] = pv1;
    }
    __syncthreads();   // z now consumed cross-warp

    // ---- GEMM phase: warp pair (2p, 2p+1) over rows 8p..8p+7, j-split ----
    int p = warp >> 1;         // row group
    int h = warp & 1;          // j-half: h*80 .. h*80+79
    int g = hb, o = l4;
    int R = p * 8 + g * 4;     // this thread's 4 rows
    const float* zb = zsh + R * 160 + h * 80;
    const ulonglong2* Wb = WT4 + h * 40 * 16 + o;

    ull acc[4][2];
    #pragma unroll
    for (int k = 0; k < 4; k++) { acc[k][0] = 0ull; acc[k][1] = 0ull; }

    #pragma unroll 2
    for (int it = 0; it < 20; it++) {
        ulonglong2 wv0 = Wb[(2 * it) * 16];
        ulonglong2 wv1 = Wb[(2 * it + 1) * 16];
        #pragma unroll
        for (int k = 0; k < 4; k++) {
            ulonglong2 zv = *(const ulonglong2*)(zb + k * 160 + it * 4);
            FMA2(acc[k][0], zv.x, wv0.x);  FMA2(acc[k][1], zv.x, wv0.y);
            FMA2(acc[k][0], zv.y, wv1.x);  FMA2(acc[k][1], zv.y, wv1.y);
        }
    }

    union U { ull u; float2 f; } uv;
    float lo[4], hi[4];
    #pragma unroll
    for (int k = 0; k < 4; k++) {
        uv.u = acc[k][0]; lo[k] = uv.f.x + uv.f.y;
        uv.u = acc[k][1]; hi[k] = uv.f.x + uv.f.y;
    }

    __syncthreads();           // z region dead; safe to reuse as partial buf
    float* pbuf = zsh;         // [32][32]
    if (h == 1) {
        #pragma unroll
        for (int k = 0; k < 4; k++) {
            pbuf[(R + k) * 32 + o]      = lo[k];
            pbuf[(R + k) * 32 + o + 16] = hi[k];
        }
    }
    __syncthreads();

    if (h == 0) {
        float blo = biastot[o], bhi = biastot[o + 16];
        float slo = 0.f, sslo = 0.f, shi = 0.f, sshi = 0.f;
        #pragma unroll
        for (int k = 0; k < 4; k++) {
            float L = lo[k] + pbuf[(R + k) * 32 + o]      + blo;
            float H = fmaxf(hi[k] + pbuf[(R + k) * 32 + o + 16] + bhi, 0.f);
            int row = row0 + R + k;
            outp[row * FF + o]      = L;
            outp[row * FF + o + 16] = H;
            slo += L;  sslo += L * L;
            shi += H;  sshi += H * H;
        }
        // fold g=0 / g=1 (same cols, different rows), then shared atomics
        slo  += __shfl_xor_sync(0xffffffffu, slo, 16);
        sslo += __shfl_xor_sync(0xffffffffu, sslo, 16);
        shi  += __shfl_xor_sync(0xffffffffu, shi, 16);
        sshi += __shfl_xor_sync(0xffffffffu, sshi, 16);
        if (lane < 16) {
            atomicAdd(&s_sum[o],      slo);
            atomicAdd(&s_ssq[o],      sslo);
            atomicAdd(&s_sum[o + 16], shi);
            atomicAdd(&s_ssq[o + 16], sshi);
        }
    }
    __syncthreads();
    if (tid < 32) {
        atomicAdd(&stats[tid],      s_sum[tid]);
        atomicAdd(&stats[32 + tid], s_ssq[tid]);
    }
}

// ---------------------------------------------------------------------------
__global__ void k_norm(float* __restrict__ out,
                       const float* __restrict__ bnxw, const float* __restrict__ bnxb,
                       const float* __restrict__ bnyw, const float* __restrict__ bnyb)
{
    int i = blockIdx.x * 256 + threadIdx.x;       // [0, (NN+EE)*8), exact
    int c0 = (i & 7) * 4;
    bool isx = i < NN * 8;
    int base = isx ? 0 : 64;
    float cnt = isx ? (float)NN : (float)EE;
    const float* wv = isx ? bnxw : bnyw;
    const float* bv = isx ? bnxb : bnyb;
    float4 v = ((float4*)out)[i];
    float* vp = (float*)&v;
    #pragma unroll
    for (int k = 0; k < 4; k++) {
        int c = c0 + k;
        float mean = g_stats[base + c] / cnt;
        float var  = g_stats[base + 32 + c] / cnt - mean * mean;
        vp[k] = (vp[k] - mean) * rsqrtf(var + EPS) * wv[c] + bv[c];
    }
    ((float4*)out)[i] = v;
}

// ---------------------------------------------------------------------------
extern "C" void kernel_launch(void* const* d_in, const int* in_sizes, int n_in,
                              void* d_out, int out_size)
{
    const float* x        = (const float*)d_in[0];
    const float* y        = (const float*)d_in[1];
    const float* deg_g    = (const float*)d_in[2];
    const float* deg_lg   = (const float*)d_in[3];
    const int*   t_g      = (const int*)d_in[4];
    const int*   tt_g     = (const int*)d_in[5];
    const int*   t_lg     = (const int*)d_in[6];
    const int*   tt_lg    = (const int*)d_in[7];
    const int*   dst      = (const int*)d_in[8];
    const int*   pm_pd    = (const int*)d_in[9];
    const float* theta_x_w   = (const float*)d_in[10];
    const float* theta_x_b   = (const float*)d_in[11];
    const float* theta_deg_w = (const float*)d_in[12];
    const float* theta_deg_b = (const float*)d_in[13];
    const float* theta_y_w   = (const float*)d_in[14];
    const float* theta_y_b   = (const float*)d_in[15];
    const float* gamma_y_w   = (const float*)d_in[16];
    const float* gamma_y_b   = (const float*)d_in[17];
    const float* gamma_deg_w = (const float*)d_in[18];
    const float* gamma_deg_b = (const float*)d_in[19];
    const float* gamma_x_w   = (const float*)d_in[20];
    const float* gamma_x_b   = (const float*)d_in[21];
    const float* theta_r_w   = (const float*)d_in[22];  // [2,32,32]
    const float* theta_r_b   = (const float*)d_in[23];  // [2,32]
    const float* gamma_r_w   = (const float*)d_in[24];
    const float* gamma_r_b   = (const float*)d_in[25];
    const float* bn_x_w      = (const float*)d_in[26];
    const float* bn_x_b      = (const float*)d_in[27];
    const float* bn_y_w      = (const float*)d_in[28];
    const float* bn_y_b      = (const float*)d_in[29];
    float* out = (float*)d_out;

    cudaFuncSetAttribute(k_main, cudaFuncAttributeMaxDynamicSharedMemorySize,
                         SMEM_BYTES);

    k_zero<<<NN * 8 / 256, 256>>>();
    k_scatter<<<EE * 16 / 256, 256>>>(y, dst);

    // Node side: z = [x, deg*x, agg_t, agg_tt, pmpd_y]
    k_main<<<NN / RPB, 256, SMEM_BYTES>>>(
        x, deg_g, t_g, tt_g, /*psrc=*/nullptr, /*pidx=*/nullptr,
        theta_x_w, theta_deg_w, theta_r_w, theta_r_w + 1024, theta_y_w,
        theta_x_b, theta_deg_b, theta_r_b, theta_r_b + 32, theta_y_b,
        out, /*statoff=*/0);

    // Edge side: z = [y, deg*y, agg_t, agg_tt, x[pm_pd]]
    k_main<<<EE / RPB, 256, SMEM_BYTES>>>(
        y, deg_lg, t_lg, tt_lg, /*psrc=*/x, /*pidx=*/pm_pd,
        gamma_y_w, gamma_deg_w, gamma_r_w, gamma_r_w + 1024, gamma_x_w,
        gamma_y_b, gamma_deg_b, gamma_r_b, gamma_r_b + 32, gamma_x_b,
        out + NN * FF, /*statoff=*/64);

    k_norm<<<(NN + EE) * 8 / 256, 256>>>(out, bn_x_w, bn_x_b, bn_y_w, bn_y_b);
}

// round 11
// speedup vs baseline: 1.0404x; 1.0404x over previous
#include <cuda_runtime.h>

#define NN 100000
#define EE 200000
#define KK 16
#define FF 32
#define EPS 1e-5f
#define RPB 64      // rows per block; warp owns 8 rows end-to-end
#define SMEM_BYTES (RPB*160*4 + 80*16*16)   // zsh 40960 + WT4 20480 = 61440

typedef unsigned long long ull;

// Scratch (static device globals — no allocation).
__device__ float g_pmpd[NN * FF];   // segment_sum(y, dst) -> [N, F]
__device__ float g_stats[128];      // [xsum32 | xssq32 | ysum32 | yssq32]

#define FMA2(acc, a, b) asm("fma.rn.f32x2 %0, %1, %2, %0;" : "+l"(acc) : "l"(a), "l"(b))
#define FADD2(acc, a)   asm("add.rn.f32x2 %0, %0, %1;"     : "+l"(acc) : "l"(a))

// ---------------------------------------------------------------------------
__global__ void k_zero() {
    int i = blockIdx.x * 256 + threadIdx.x;      // [0, NN*8)
    ((float4*)g_pmpd)[i] = make_float4(0.f, 0.f, 0.f, 0.f);
    if (i < 128) g_stats[i] = 0.f;
}

// segment_sum: vectorized f32x2 global reductions (red.global.add.v2.f32).
__global__ void k_scatter(const float* __restrict__ y, const int* __restrict__ dst) {
    int i = blockIdx.x * 256 + threadIdx.x;   // [0, EE*16), exact
    int e = i >> 4, c = i & 15;               // 16 float2 chunks per 32-f row
    int d = __ldg(&dst[e]);
    float2 v = ((const float2*)y)[i];
    float* p = g_pmpd + d * FF + c * 2;
    asm volatile("{\n\t.reg .u64 q;\n\tcvta.to.global.u64 q, %0;\n\t"
                 "red.global.add.v2.f32 [q], {%1, %2};\n\t}"
                 :: "l"(p), "f"(v.x), "f"(v.y) : "memory");
}

// ---------------------------------------------------------------------------
// Fused per-row kernel. Row z = [v, deg*v, sum_t, sum_tt, p] (160 floats),
// out = z @ Wbig + bias ; relu cols [16:32) ; BN stats accumulation.
// 256 threads = 8 warps; warp owns 8 rows END-TO-END (gather then GEMM),
// __syncwarp only — no cross-warp coupling (R9 lesson). W wavefronts amortize
// over 8 rows. 3 blocks/SM (smem-limited), 85 regs/thread for deep MLP.
// ---------------------------------------------------------------------------
__global__ __launch_bounds__(256, 3) void k_main(
    const float* __restrict__ feat, const float* __restrict__ deg,
    const int* __restrict__ t, const int* __restrict__ tt,
    const float* __restrict__ psrc, const int* __restrict__ pidx,
    const float* __restrict__ w0, const float* __restrict__ w1,
    const float* __restrict__ w2, const float* __restrict__ w3,
    const float* __restrict__ w4,
    const float* __restrict__ b0, const float* __restrict__ b1,
    const float* __restrict__ b2, const float* __restrict__ b3,
    const float* __restrict__ b4,
    float* __restrict__ outp, int statoff, int nrows)
{
    extern __shared__ char smem[];
    float* zsh = (float*)smem;                          // [RPB][160]
    float4* WT4s = (float4*)(smem + RPB * 160 * 4);     // [80][16] staging view
    const ulonglong2* WT4 = (const ulonglong2*)WT4s;    // read view
    __shared__ float biastot[32];
    __shared__ float s_sum[32], s_ssq[32];

    const float* pbase = psrc ? psrc : g_pmpd;
    float* stats = g_stats + statoff;

    int tid = threadIdx.x;
    // Stage packed weights: WT4[j2*16+o] = {W[2j2][o], W[2j2+1][o],
    //                                       W[2j2][o+16], W[2j2+1][o+16]}
    for (int i = tid; i < 80 * 16; i += 256) {
        int j2 = i >> 4, o = i & 15;
        int j = 2 * j2;
        const float* src = (j < 32) ? w0 : (j < 64) ? w1 : (j < 96) ? w2
                                   : (j < 128) ? w3 : w4;
        int jr = j & 31;
        WT4s[i] = make_float4(src[jr * 32 + o],        src[(jr + 1) * 32 + o],
                              src[jr * 32 + o + 16],   src[(jr + 1) * 32 + o + 16]);
    }
    if (tid < 32) {
        biastot[tid] = b0[tid] + b1[tid] + b2[tid] + b3[tid] + b4[tid];
        s_sum[tid] = 0.f; s_ssq[tid] = 0.f;
    }
    __syncthreads();

    int lane = tid & 31, warp = tid >> 5;
    int row0 = blockIdx.x * RPB;
    int rbase = warp * 8;                 // 8 rows per warp
    int l4 = lane & 15;
    int hb = lane >> 4;
    const ull* fb = (const ull*)feat;     // feat as float2 (8B) elements

    // nrows ≡ 0 (mod 8) and rows come in warp-owned 8-blocks -> warp-uniform
    bool wvalid = (row0 + rbase) < nrows;
    if (wvalid) {
        // ---- Gather phase: 8 rows, 2 interleaved at a time ----
        #pragma unroll
        for (int s = 0; s < 8; s += 2) {
            int m0 = rbase + s, m1 = m0 + 1;
            int n0 = row0 + m0, n1 = row0 + m1;
            float xv0 = feat[n0 * FF + lane];
            float xv1 = feat[n1 * FF + lane];
            float dv0 = deg[n0] * xv0;
            float dv1 = deg[n1] * xv1;
            int ir0 = (lane < 16) ? t[n0 * KK + lane] : tt[n0 * KK + lane - 16];
            int ir1 = (lane < 16) ? t[n1 * KK + lane] : tt[n1 * KK + lane - 16];

            ull a00 = 0ull, a01 = 0ull, a10 = 0ull, a11 = 0ull;
            #pragma unroll
            for (int q = 0; q < 8; q++) {
                int sl = 2 * q + hb;
                int i00 = __shfl_sync(0xffffffffu, ir0, sl);
                int i01 = __shfl_sync(0xffffffffu, ir0, sl + 16);
                int i10 = __shfl_sync(0xffffffffu, ir1, sl);
                int i11 = __shfl_sync(0xffffffffu, ir1, sl + 16);
                ull v00 = fb[i00 * 16 + l4];
                ull v01 = fb[i01 * 16 + l4];
                ull v10 = fb[i10 * 16 + l4];
                ull v11 = fb[i11 * 16 + l4];
                FADD2(a00, v00);
                FADD2(a01, v01);
                FADD2(a10, v10);
                FADD2(a11, v11);
            }
            ull f00 = __shfl_xor_sync(0xffffffffu, a00, 16); FADD2(a00, f00);
            ull f01 = __shfl_xor_sync(0xffffffffu, a01, 16); FADD2(a01, f01);
            ull f10 = __shfl_xor_sync(0xffffffffu, a10, 16); FADD2(a10, f10);
            ull f11 = __shfl_xor_sync(0xffffffffu, a11, 16); FADD2(a11, f11);

            float pv0 = pidx ? pbase[pidx[n0] * FF + lane] : pbase[n0 * FF + lane];
            float pv1 = pidx ? pbase[pidx[n1] * FF + lane] : pbase[n1 * FF + lane];
            float* zr0 = zsh + m0 * 160;
            float* zr1 = zsh + m1 * 160;
            zr0[lane] = xv0;       zr1[lane] = xv1;
            zr0[32 + lane] = dv0;  zr1[32 + lane] = dv1;
            union Uc { ull u; float2 f; } c0, c1;
            c0.u = hb ? a01 : a00;
            c1.u = hb ? a11 : a10;
            int zo = (hb ? 96 : 64) + 2 * l4;
            *(float2*)(zr0 + zo) = c0.f;
            *(float2*)(zr1 + zo) = c1.f;
            zr0[128 + lane] = pv0; zr1[128 + lane] = pv1;
        }
        __syncwarp();   // z produced & consumed within the same warp only

        // ---- GEMM phase: thread = 4 rows (g selects quad) x col-pair ----
        int g = hb, o = l4;
        int mA = rbase + g * 4;           // rows mA..mA+3
        const float* z0 = zsh + mA * 160;

        ull acc[4][2];
        #pragma unroll
        for (int k = 0; k < 4; k++) { acc[k][0] = 0ull; acc[k][1] = 0ull; }

        #pragma unroll 4
        for (int it = 0; it < 40; it++) {
            ulonglong2 wv0 = WT4[(2 * it) * 16 + o];
            ulonglong2 wv1 = WT4[(2 * it + 1) * 16 + o];
            #pragma unroll
            for (int k = 0; k < 4; k++) {
                ulonglong2 zv = *(const ulonglong2*)(z0 + k * 160 + it * 4);
                FMA2(acc[k][0], zv.x, wv0.x);  FMA2(acc[k][1], zv.x, wv0.y);
                FMA2(acc[k][0], zv.y, wv1.x);  FMA2(acc[k][1], zv.y, wv1.y);
            }
        }

        union U { ull u; float2 f; } uv;
        float blo = biastot[o], bhi = biastot[o + 16];
        float slo = 0.f, sslo = 0.f, shi = 0.f, sshi = 0.f;
        #pragma unroll
        for (int k = 0; k < 4; k++) {
            uv.u = acc[k][0]; float L = uv.f.x + uv.f.y + blo;
            uv.u = acc[k][1]; float H = fmaxf(uv.f.x + uv.f.y + bhi, 0.f);
            int row = row0 + mA + k;
            outp[row * FF + o]      = L;
            outp[row * FF + o + 16] = H;
            slo += L;  sslo += L * L;
            shi += H;  sshi += H * H;
        }
        // fold g=0 / g=1 (same cols, different rows), then shared atomics
        slo  += __shfl_xor_sync(0xffffffffu, slo, 16);
        sslo += __shfl_xor_sync(0xffffffffu, sslo, 16);
        shi  += __shfl_xor_sync(0xffffffffu, shi, 16);
        sshi += __shfl_xor_sync(0xffffffffu, sshi, 16);
        if (lane < 16) {
            atomicAdd(&s_sum[o],      slo);
            atomicAdd(&s_ssq[o],      sslo);
            atomicAdd(&s_sum[o + 16], shi);
            atomicAdd(&s_ssq[o + 16], sshi);
        }
    }
    __syncthreads();
    if (tid < 32) {
        atomicAdd(&stats[tid],      s_sum[tid]);
        atomicAdd(&stats[32 + tid], s_ssq[tid]);
    }
}

// ---------------------------------------------------------------------------
__global__ void k_norm(float* __restrict__ out,
                       const float* __restrict__ bnxw, const float* __restrict__ bnxb,
                       const float* __restrict__ bnyw, const float* __restrict__ bnyb)
{
    int i = blockIdx.x * 256 + threadIdx.x;       // [0, (NN+EE)*8), exact
    int c0 = (i & 7) * 4;
    bool isx = i < NN * 8;
    int base = isx ? 0 : 64;
    float cnt = isx ? (float)NN : (float)EE;
    const float* wv = isx ? bnxw : bnyw;
    const float* bv = isx ? bnxb : bnyb;
    float4 v = ((float4*)out)[i];
    float* vp = (float*)&v;
    #pragma unroll
    for (int k = 0; k < 4; k++) {
        int c = c0 + k;
        float mean = g_stats[base + c] / cnt;
        float var  = g_stats[base + 32 + c] / cnt - mean * mean;
        vp[k] = (vp[k] - mean) * rsqrtf(var + EPS) * wv[c] + bv[c];
    }
    ((float4*)out)[i] = v;
}

// ---------------------------------------------------------------------------
extern "C" void kernel_launch(void* const* d_in, const int* in_sizes, int n_in,
                              void* d_out, int out_size)
{
    const float* x        = (const float*)d_in[0];
    const float* y        = (const float*)d_in[1];
    const float* deg_g    = (const float*)d_in[2];
    const float* deg_lg   = (const float*)d_in[3];
    const int*   t_g      = (const int*)d_in[4];
    const int*   tt_g     = (const int*)d_in[5];
    const int*   t_lg     = (const int*)d_in[6];
    const int*   tt_lg    = (const int*)d_in[7];
    const int*   dst      = (const int*)d_in[8];
    const int*   pm_pd    = (const int*)d_in[9];
    const float* theta_x_w   = (const float*)d_in[10];
    const float* theta_x_b   = (const float*)d_in[11];
    const float* theta_deg_w = (const float*)d_in[12];
    const float* theta_deg_b = (const float*)d_in[13];
    const float* theta_y_w   = (const float*)d_in[14];
    const float* theta_y_b   = (const float*)d_in[15];
    const float* gamma_y_w   = (const float*)d_in[16];
    const float* gamma_y_b   = (const float*)d_in[17];
    const float* gamma_deg_w = (const float*)d_in[18];
    const float* gamma_deg_b = (const float*)d_in[19];
    const float* gamma_x_w   = (const float*)d_in[20];
    const float* gamma_x_b   = (const float*)d_in[21];
    const float* theta_r_w   = (const float*)d_in[22];  // [2,32,32]
    const float* theta_r_b   = (const float*)d_in[23];  // [2,32]
    const float* gamma_r_w   = (const float*)d_in[24];
    const float* gamma_r_b   = (const float*)d_in[25];
    const float* bn_x_w      = (const float*)d_in[26];
    const float* bn_x_b      = (const float*)d_in[27];
    const float* bn_y_w      = (const float*)d_in[28];
    const float* bn_y_b      = (const float*)d_in[29];
    float* out = (float*)d_out;

    cudaFuncSetAttribute(k_main, cudaFuncAttributeMaxDynamicSharedMemorySize,
                         SMEM_BYTES);

    k_zero<<<NN * 8 / 256, 256>>>();
    k_scatter<<<EE * 16 / 256, 256>>>(y, dst);

    // Node side: z = [x, deg*x, agg_t, agg_tt, pmpd_y]  (tail: 100000 % 64 = 32)
    k_main<<<(NN + RPB - 1) / RPB, 256, SMEM_BYTES>>>(
        x, deg_g, t_g, tt_g, /*psrc=*/nullptr, /*pidx=*/nullptr,
        theta_x_w, theta_deg_w, theta_r_w, theta_r_w + 1024, theta_y_w,
        theta_x_b, theta_deg_b, theta_r_b, theta_r_b + 32, theta_y_b,
        out, /*statoff=*/0, NN);

    // Edge side: z = [y, deg*y, agg_t, agg_tt, x[pm_pd]]
    k_main<<<EE / RPB, 256, SMEM_BYTES>>>(
        y, deg_lg, t_lg, tt_lg, /*psrc=*/x, /*pidx=*/pm_pd,
        gamma_y_w, gamma_deg_w, gamma_r_w, gamma_r_w + 1024, gamma_x_w,
        gamma_y_b, gamma_deg_b, gamma_r_b, gamma_r_b + 32, gamma_x_b,
        out + NN * FF, /*statoff=*/64, EE);

    k_norm<<<(NN + EE) * 8 / 256, 256>>>(out, bn_x_w, bn_x_b, bn_y_w, bn_y_b);
}

// round 13
// speedup vs baseline: 1.1600x; 1.1149x over previous
#include <cuda_runtime.h>

#define NN 100000
#define EE 200000
#define KK 16
#define FF 32
#define EPS 1e-5f
#define RPB 32      // rows per block (NN, EE both divide exactly)
#define SMEM_BYTES (RPB*160*4 + 80*16*16)   // zsh 20480 + WT4 20480 = 40960

typedef unsigned long long ull;

// Scratch (static device globals — no allocation).
__device__ float g_pmpd[NN * FF];   // segment_sum(y, dst) -> [N, F]
__device__ float g_stats[128];      // [xsum32 | xssq32 | ysum32 | yssq32]

#define FMA2(acc, a, b) asm("fma.rn.f32x2 %0, %1, %2, %0;" : "+l"(acc) : "l"(a), "l"(b))
#define FADD2(acc, a)   asm("add.rn.f32x2 %0, %0, %1;"     : "+l"(acc) : "l"(a))

// ---------------------------------------------------------------------------
__global__ void k_zero() {
    int i = blockIdx.x * 256 + threadIdx.x;      // [0, NN*8)
    ((float4*)g_pmpd)[i] = make_float4(0.f, 0.f, 0.f, 0.f);
    if (i < 128) g_stats[i] = 0.f;
}

// segment_sum: vectorized f32x2 global reductions (red.global.add.v2.f32).
__global__ void k_scatter(const float* __restrict__ y, const int* __restrict__ dst) {
    int i = blockIdx.x * 256 + threadIdx.x;   // [0, EE*16), exact
    int e = i >> 4, c = i & 15;               // 16 float2 chunks per 32-f row
    int d = __ldg(&dst[e]);
    float2 v = ((const float2*)y)[i];
    float* p = g_pmpd + d * FF + c * 2;
    asm volatile("{\n\t.reg .u64 q;\n\tcvta.to.global.u64 q, %0;\n\t"
                 "red.global.add.v2.f32 [q], {%1, %2};\n\t}"
                 :: "l"(p), "f"(v.x), "f"(v.y) : "memory");
}

// ---------------------------------------------------------------------------
// Fused per-row kernel. Row z = [v, deg*v, sum_t, sum_tt, p] (160 floats),
// out = z @ Wbig + bias ; relu cols [16:32) ; BN stats accumulation.
// 256 threads = 8 warps = 32 rows/block (5 blocks/SM, 62.5% occ).
//   Gather: identical to R8 — warp gathers 4 rows, LDG.64 2-rows/instr.
//   GEMM:   o-split warp PAIRS. Warps (2p, 2p+1) share rows 8p..8p+7; each
//           warp covers 8 col-pairs (warp&1 selects o range). Thread =
//           (rq = lane>>3 -> 2 rows, o4 = lane&7). W LDS = 8 distinct addrs
//           = 1 wavefront amortized over 8 rows (4x less W traffic than R8).
//           Pair-local bar.sync(64) only — no block-wide lockstep.
// ---------------------------------------------------------------------------
__global__ __launch_bounds__(256, 5) void k_main(
    const float* __restrict__ feat, const float* __restrict__ deg,
    const int* __restrict__ t, const int* __restrict__ tt,
    const float* __restrict__ psrc, const int* __restrict__ pidx,
    const float* __restrict__ w0, const float* __restrict__ w1,
    const float* __restrict__ w2, const float* __restrict__ w3,
    const float* __restrict__ w4,
    const float* __restrict__ b0, const float* __restrict__ b1,
    const float* __restrict__ b2, const float* __restrict__ b3,
    const float* __restrict__ b4,
    float* __restrict__ outp, int statoff)
{
    extern __shared__ char smem[];
    float* zsh = (float*)smem;                          // [RPB][160]
    float4* WT4s = (float4*)(smem + RPB * 160 * 4);     // [80][16] staging view
    const ulonglong2* WT4 = (const ulonglong2*)WT4s;    // read view
    __shared__ float biastot[32];
    __shared__ float s_sum[32], s_ssq[32];

    const float* pbase = psrc ? psrc : g_pmpd;
    float* stats = g_stats + statoff;

    int tid = threadIdx.x;
    // Stage packed weights: WT4[j2*16+o] = {W[2j2][o], W[2j2+1][o],
    //                                       W[2j2][o+16], W[2j2+1][o+16]}
    for (int i = tid; i < 80 * 16; i += 256) {
        int j2 = i >> 4, o = i & 15;
        int j = 2 * j2;
        const float* src = (j < 32) ? w0 : (j < 64) ? w1 : (j < 96) ? w2
                                   : (j < 128) ? w3 : w4;
        int jr = j & 31;
        WT4s[i] = make_float4(src[jr * 32 + o],        src[(jr + 1) * 32 + o],
                              src[jr * 32 + o + 16],   src[(jr + 1) * 32 + o + 16]);
    }
    if (tid < 32) {
        biastot[tid] = b0[tid] + b1[tid] + b2[tid] + b3[tid] + b4[tid];
        s_sum[tid] = 0.f; s_ssq[tid] = 0.f;
    }
    __syncthreads();

    int lane = tid & 31, warp = tid >> 5;
    int row0 = blockIdx.x * RPB;
    int rbase = warp * 4;                 // 4 rows gathered per warp
    int l4 = lane & 15;
    int hb = lane >> 4;
    const ull* fb = (const ull*)feat;     // feat as float2 (8B) elements

    // ---- Gather phase (R8-proven): 2 interleaved rows at a time ----
    #pragma unroll
    for (int s = 0; s < 4; s += 2) {
        int m0 = rbase + s, m1 = m0 + 1;
        int n0 = row0 + m0, n1 = row0 + m1;
        float xv0 = feat[n0 * FF + lane];
        float xv1 = feat[n1 * FF + lane];
        float dv0 = deg[n0] * xv0;
        float dv1 = deg[n1] * xv1;
        int ir0 = (lane < 16) ? t[n0 * KK + lane] : tt[n0 * KK + lane - 16];
        int ir1 = (lane < 16) ? t[n1 * KK + lane] : tt[n1 * KK + lane - 16];

        ull a00 = 0ull, a01 = 0ull, a10 = 0ull, a11 = 0ull;
        #pragma unroll
        for (int q = 0; q < 8; q++) {
            int sl = 2 * q + hb;
            int i00 = __shfl_sync(0xffffffffu, ir0, sl);
            int i01 = __shfl_sync(0xffffffffu, ir0, sl + 16);
            int i10 = __shfl_sync(0xffffffffu, ir1, sl);
            int i11 = __shfl_sync(0xffffffffu, ir1, sl + 16);
            ull v00 = fb[i00 * 16 + l4];
            ull v01 = fb[i01 * 16 + l4];
            ull v10 = fb[i10 * 16 + l4];
            ull v11 = fb[i11 * 16 + l4];
            FADD2(a00, v00);
            FADD2(a01, v01);
            FADD2(a10, v10);
            FADD2(a11, v11);
        }
        ull f00 = __shfl_xor_sync(0xffffffffu, a00, 16); FADD2(a00, f00);
        ull f01 = __shfl_xor_sync(0xffffffffu, a01, 16); FADD2(a01, f01);
        ull f10 = __shfl_xor_sync(0xffffffffu, a10, 16); FADD2(a10, f10);
        ull f11 = __shfl_xor_sync(0xffffffffu, a11, 16); FADD2(a11, f11);

        float pv0 = pidx ? pbase[pidx[n0] * FF + lane] : pbase[n0 * FF + lane];
        float pv1 = pidx ? pbase[pidx[n1] * FF + lane] : pbase[n1 * FF + lane];
        float* zr0 = zsh + m0 * 160;
        float* zr1 = zsh + m1 * 160;
        zr0[lane] = xv0;       zr1[lane] = xv1;
        zr0[32 + lane] = dv0;  zr1[32 + lane] = dv1;
        union Uc { ull u; float2 f; } c0, c1;
        c0.u = hb ? a01 : a00;
        c1.u = hb ? a11 : a10;
        int zo = (hb ? 96 : 64) + 2 * l4;
        *(float2*)(zr0 + zo) = c0.f;
        *(float2*)(zr1 + zo) = c1.f;
        zr0[128 + lane] = pv0; zr1[128 + lane] = pv1;
    }

    // Pair-local barrier: warps (2p, 2p+1) exchange their 8 rows of z.
    int pair = warp >> 1;
    asm volatile("bar.sync %0, 64;" :: "r"(pair + 1) : "memory");

    // ---- GEMM phase: pair shares rows 8p..8p+7; warp covers 8 col-pairs ----
    int og = ((warp & 1) << 3) | (lane & 7);   // col pair (og, og+16)
    int rq = lane >> 3;                        // row pair within the 8
    int R = pair * 8 + rq * 2;                 // rows R, R+1
    const float* zA = zsh + R * 160;
    const float* zB = zsh + (R + 1) * 160;

    ull aAlo = 0ull, aAhi = 0ull, aBlo = 0ull, aBhi = 0ull;
    #pragma unroll 4
    for (int it = 0; it < 40; it++) {
        ulonglong2 wv0 = WT4[(2 * it) * 16 + og];      // 8 distinct addrs: 1 wf
        ulonglong2 wv1 = WT4[(2 * it + 1) * 16 + og];
        ulonglong2 za = *(const ulonglong2*)(zA + it * 4);
        ulonglong2 zb = *(const ulonglong2*)(zB + it * 4);
        FMA2(aAlo, za.x, wv0.x);  FMA2(aAhi, za.x, wv0.y);
        FMA2(aAlo, za.y, wv1.x);  FMA2(aAhi, za.y, wv1.y);
        FMA2(aBlo, zb.x, wv0.x);  FMA2(aBhi, zb.x, wv0.y);
        FMA2(aBlo, zb.y, wv1.x);  FMA2(aBhi, zb.y, wv1.y);
    }

    union U { ull u; float2 f; } uv;
    float blo = biastot[og], bhi = biastot[og + 16];
    uv.u = aAlo; float LA = uv.f.x + uv.f.y + blo;
    uv.u = aAhi; float HA = fmaxf(uv.f.x + uv.f.y + bhi, 0.f);
    uv.u = aBlo; float LB = uv.f.x + uv.f.y + blo;
    uv.u = aBhi; float HB = fmaxf(uv.f.x + uv.f.y + bhi, 0.f);

    int rowA = row0 + R;
    outp[rowA * FF + og]            = LA;
    outp[rowA * FF + og + 16]       = HA;
    outp[(rowA + 1) * FF + og]      = LB;
    outp[(rowA + 1) * FF + og + 16] = HB;

    // BN stats: fold 2 rows in-thread, fold rq (lane bits 3,4), shared atomics.
    float slo = LA + LB,  sslo = LA * LA + LB * LB;
    float shi = HA + HB,  sshi = HA * HA + HB * HB;
    slo  += __shfl_xor_sync(0xffffffffu, slo, 8);
    sslo += __shfl_xor_sync(0xffffffffu, sslo, 8);
    shi  += __shfl_xor_sync(0xffffffffu, shi, 8);
    sshi += __shfl_xor_sync(0xffffffffu, sshi, 8);
    slo  += __shfl_xor_sync(0xffffffffu, slo, 16);
    sslo += __shfl_xor_sync(0xffffffffu, sslo, 16);
    shi  += __shfl_xor_sync(0xffffffffu, shi, 16);
    sshi += __shfl_xor_sync(0xffffffffu, sshi, 16);
    if (lane < 8) {
        atomicAdd(&s_sum[og],      slo);
        atomicAdd(&s_ssq[og],      sslo);
        atomicAdd(&s_sum[og + 16], shi);
        atomicAdd(&s_ssq[og + 16], sshi);
    }
    __syncthreads();
    if (tid < 32) {
        atomicAdd(&stats[tid],      s_sum[tid]);
        atomicAdd(&stats[32 + tid], s_ssq[tid]);
    }
}

// ---------------------------------------------------------------------------
__global__ void k_norm(float* __restrict__ out,
                       const float* __restrict__ bnxw, const float* __restrict__ bnxb,
                       const float* __restrict__ bnyw, const float* __restrict__ bnyb)
{
    int i = blockIdx.x * 256 + threadIdx.x;       // [0, (NN+EE)*8), exact
    int c0 = (i & 7) * 4;
    bool isx = i < NN * 8;
    int base = isx ? 0 : 64;
    float cnt = isx ? (float)NN : (float)EE;
    const float* wv = isx ? bnxw : bnyw;
    const float* bv = isx ? bnxb : bnyb;
    float4 v = ((float4*)out)[i];
    float* vp = (float*)&v;
    #pragma unroll
    for (int k = 0; k < 4; k++) {
        int c = c0 + k;
        float mean = g_stats[base + c] / cnt;
        float var  = g_stats[base + 32 + c] / cnt - mean * mean;
        vp[k] = (vp[k] - mean) * rsqrtf(var + EPS) * wv[c] + bv[c];
    }
    ((float4*)out)[i] = v;
}

// ---------------------------------------------------------------------------
extern "C" void kernel_launch(void* const* d_in, const int* in_sizes, int n_in,
                              void* d_out, int out_size)
{
    const float* x        = (const float*)d_in[0];
    const float* y        = (const float*)d_in[1];
    const float* deg_g    = (const float*)d_in[2];
    const float* deg_lg   = (const float*)d_in[3];
    const int*   t_g      = (const int*)d_in[4];
    const int*   tt_g     = (const int*)d_in[5];
    const int*   t_lg     = (const int*)d_in[6];
    const int*   tt_lg    = (const int*)d_in[7];
    const int*   dst      = (const int*)d_in[8];
    const int*   pm_pd    = (const int*)d_in[9];
    const float* theta_x_w   = (const float*)d_in[10];
    const float* theta_x_b   = (const float*)d_in[11];
    const float* theta_deg_w = (const float*)d_in[12];
    const float* theta_deg_b = (const float*)d_in[13];
    const float* theta_y_w   = (const float*)d_in[14];
    const float* theta_y_b   = (const float*)d_in[15];
    const float* gamma_y_w   = (const float*)d_in[16];
    const float* gamma_y_b   = (const float*)d_in[17];
    const float* gamma_deg_w = (const float*)d_in[18];
    const float* gamma_deg_b = (const float*)d_in[19];
    const float* gamma_x_w   = (const float*)d_in[20];
    const float* gamma_x_b   = (const float*)d_in[21];
    const float* theta_r_w   = (const float*)d_in[22];  // [2,32,32]
    const float* theta_r_b   = (const float*)d_in[23];  // [2,32]
    const float* gamma_r_w   = (const float*)d_in[24];
    const float* gamma_r_b   = (const float*)d_in[25];
    const float* bn_x_w      = (const float*)d_in[26];
    const float* bn_x_b      = (const float*)d_in[27];
    const float* bn_y_w      = (const float*)d_in[28];
    const float* bn_y_b      = (const float*)d_in[29];
    float* out = (float*)d_out;

    cudaFuncSetAttribute(k_main, cudaFuncAttributeMaxDynamicSharedMemorySize,
                         SMEM_BYTES);

    k_zero<<<NN * 8 / 256, 256>>>();
    k_scatter<<<EE * 16 / 256, 256>>>(y, dst);

    // Node side: z = [x, deg*x, agg_t, agg_tt, pmpd_y]
    k_main<<<NN / RPB, 256, SMEM_BYTES>>>(
        x, deg_g, t_g, tt_g, /*psrc=*/nullptr, /*pidx=*/nullptr,
        theta_x_w, theta_deg_w, theta_r_w, theta_r_w + 1024, theta_y_w,
        theta_x_b, theta_deg_b, theta_r_b, theta_r_b + 32, theta_y_b,
        out, /*statoff=*/0);

    // Edge side: z = [y, deg*y, agg_t, agg_tt, x[pm_pd]]
    k_main<<<EE / RPB, 256, SMEM_BYTES>>>(
        y, deg_lg, t_lg, tt_lg, /*psrc=*/x, /*pidx=*/pm_pd,
        gamma_y_w, gamma_deg_w, gamma_r_w, gamma_r_w + 1024, gamma_x_w,
        gamma_y_b, gamma_deg_b, gamma_r_b, gamma_r_b + 32, gamma_x_b,
        out + NN * FF, /*statoff=*/64);

    k_norm<<<(NN + EE) * 8 / 256, 256>>>(out, bn_x_w, bn_x_b, bn_y_w, bn_y_b);
}

// round 14
// speedup vs baseline: 1.1625x; 1.0021x over previous
#include <cuda_runtime.h>

#define NN 100000
#define EE 200000
#define KK 16
#define FF 32
#define EPS 1e-5f
#define RPB 32      // rows per block (NN, EE both divide exactly)
#define SMEM_BYTES (RPB*160*4 + 80*16*16)   // zsh 20480 + WT4 20480 = 40960

typedef unsigned long long ull;

// Scratch (static device globals — no allocation).
__device__ float g_pmpd[NN * FF];   // segment_sum(y, dst) -> [N, F]
__device__ float g_stats[128];      // [xsum32 | xssq32 | ysum32 | yssq32]

#define FMA2(acc, a, b) asm("fma.rn.f32x2 %0, %1, %2, %0;" : "+l"(acc) : "l"(a), "l"(b))
#define FADD2(acc, a)   asm("add.rn.f32x2 %0, %0, %1;"     : "+l"(acc) : "l"(a))

// ---------------------------------------------------------------------------
__global__ void k_zero() {
    int i = blockIdx.x * 256 + threadIdx.x;      // [0, NN*8)
    ((float4*)g_pmpd)[i] = make_float4(0.f, 0.f, 0.f, 0.f);
    if (i < 128) g_stats[i] = 0.f;
}

// segment_sum: vectorized f32x2 global reductions (red.global.add.v2.f32).
__global__ void k_scatter(const float* __restrict__ y, const int* __restrict__ dst) {
    int i = blockIdx.x * 256 + threadIdx.x;   // [0, EE*16), exact
    int e = i >> 4, c = i & 15;               // 16 float2 chunks per 32-f row
    int d = __ldg(&dst[e]);
    float2 v = ((const float2*)y)[i];
    float* p = g_pmpd + d * FF + c * 2;
    asm volatile("{\n\t.reg .u64 q;\n\tcvta.to.global.u64 q, %0;\n\t"
                 "red.global.add.v2.f32 [q], {%1, %2};\n\t}"
                 :: "l"(p), "f"(v.x), "f"(v.y) : "memory");
}

// ---------------------------------------------------------------------------
// Fused per-row kernel. Row z = [v, deg*v, sum_t, sum_tt, p] (160 floats),
// out = z @ Wbig + bias ; relu cols [16:32) ; BN stats accumulation.
// 256 threads = 8 warps = 32 rows/block (5 blocks/SM, 62.5% occ).
//   Gather: identical to R8 — warp gathers 4 rows, LDG.64 2-rows/instr.
//   GEMM:   o-split warp PAIRS. Warps (2p, 2p+1) share rows 8p..8p+7; each
//           warp covers 8 col-pairs (warp&1 selects o range). Thread =
//           (rq = lane>>3 -> 2 rows, o4 = lane&7). W LDS = 8 distinct addrs
//           = 1 wavefront amortized over 8 rows (4x less W traffic than R8).
//           Pair-local bar.sync(64) only — no block-wide lockstep.
// ---------------------------------------------------------------------------
__global__ __launch_bounds__(256, 5) void k_main(
    const float* __restrict__ feat, const float* __restrict__ deg,
    const int* __restrict__ t, const int* __restrict__ tt,
    const float* __restrict__ psrc, const int* __restrict__ pidx,
    const float* __restrict__ w0, const float* __restrict__ w1,
    const float* __restrict__ w2, const float* __restrict__ w3,
    const float* __restrict__ w4,
    const float* __restrict__ b0, const float* __restrict__ b1,
    const float* __restrict__ b2, const float* __restrict__ b3,
    const float* __restrict__ b4,
    float* __restrict__ outp, int statoff)
{
    extern __shared__ char smem[];
    float* zsh = (float*)smem;                          // [RPB][160]
    float4* WT4s = (float4*)(smem + RPB * 160 * 4);     // [80][16] staging view
    const ulonglong2* WT4 = (const ulonglong2*)WT4s;    // read view
    __shared__ float biastot[32];
    __shared__ float s_sum[32], s_ssq[32];

    const float* pbase = psrc ? psrc : g_pmpd;
    float* stats = g_stats + statoff;

    int tid = threadIdx.x;
    // Stage packed weights: WT4[j2*16+o] = {W[2j2][o], W[2j2+1][o],
    //                                       W[2j2][o+16], W[2j2+1][o+16]}
    for (int i = tid; i < 80 * 16; i += 256) {
        int j2 = i >> 4, o = i & 15;
        int j = 2 * j2;
        const float* src = (j < 32) ? w0 : (j < 64) ? w1 : (j < 96) ? w2
                                   : (j < 128) ? w3 : w4;
        int jr = j & 31;
        WT4s[i] = make_float4(src[jr * 32 + o],        src[(jr + 1) * 32 + o],
                              src[jr * 32 + o + 16],   src[(jr + 1) * 32 + o + 16]);
    }
    if (tid < 32) {
        biastot[tid] = b0[tid] + b1[tid] + b2[tid] + b3[tid] + b4[tid];
        s_sum[tid] = 0.f; s_ssq[tid] = 0.f;
    }
    __syncthreads();

    int lane = tid & 31, warp = tid >> 5;
    int row0 = blockIdx.x * RPB;
    int rbase = warp * 4;                 // 4 rows gathered per warp
    int l4 = lane & 15;
    int hb = lane >> 4;
    const ull* fb = (const ull*)feat;     // feat as float2 (8B) elements

    // ---- Gather phase (R8-proven): 2 interleaved rows at a time ----
    #pragma unroll
    for (int s = 0; s < 4; s += 2) {
        int m0 = rbase + s, m1 = m0 + 1;
        int n0 = row0 + m0, n1 = row0 + m1;
        float xv0 = feat[n0 * FF + lane];
        float xv1 = feat[n1 * FF + lane];
        float dv0 = deg[n0] * xv0;
        float dv1 = deg[n1] * xv1;
        int ir0 = (lane < 16) ? t[n0 * KK + lane] : tt[n0 * KK + lane - 16];
        int ir1 = (lane < 16) ? t[n1 * KK + lane] : tt[n1 * KK + lane - 16];

        ull a00 = 0ull, a01 = 0ull, a10 = 0ull, a11 = 0ull;
        #pragma unroll
        for (int q = 0; q < 8; q++) {
            int sl = 2 * q + hb;
            int i00 = __shfl_sync(0xffffffffu, ir0, sl);
            int i01 = __shfl_sync(0xffffffffu, ir0, sl + 16);
            int i10 = __shfl_sync(0xffffffffu, ir1, sl);
            int i11 = __shfl_sync(0xffffffffu, ir1, sl + 16);
            ull v00 = fb[i00 * 16 + l4];
            ull v01 = fb[i01 * 16 + l4];
            ull v10 = fb[i10 * 16 + l4];
            ull v11 = fb[i11 * 16 + l4];
            FADD2(a00, v00);
            FADD2(a01, v01);
            FADD2(a10, v10);
            FADD2(a11, v11);
        }
        ull f00 = __shfl_xor_sync(0xffffffffu, a00, 16); FADD2(a00, f00);
        ull f01 = __shfl_xor_sync(0xffffffffu, a01, 16); FADD2(a01, f01);
        ull f10 = __shfl_xor_sync(0xffffffffu, a10, 16); FADD2(a10, f10);
        ull f11 = __shfl_xor_sync(0xffffffffu, a11, 16); FADD2(a11, f11);

        float pv0 = pidx ? pbase[pidx[n0] * FF + lane] : pbase[n0 * FF + lane];
        float pv1 = pidx ? pbase[pidx[n1] * FF + lane] : pbase[n1 * FF + lane];
        float* zr0 = zsh + m0 * 160;
        float* zr1 = zsh + m1 * 160;
        zr0[lane] = xv0;       zr1[lane] = xv1;
        zr0[32 + lane] = dv0;  zr1[32 + lane] = dv1;
        union Uc { ull u; float2 f; } c0, c1;
        c0.u = hb ? a01 : a00;
        c1.u = hb ? a11 : a10;
        int zo = (hb ? 96 : 64) + 2 * l4;
        *(float2*)(zr0 + zo) = c0.f;
        *(float2*)(zr1 + zo) = c1.f;
        zr0[128 + lane] = pv0; zr1[128 + lane] = pv1;
    }

    // Pair-local barrier: warps (2p, 2p+1) exchange their 8 rows of z.
    int pair = warp >> 1;
    asm volatile("bar.sync %0, 64;" :: "r"(pair + 1) : "memory");

    // ---- GEMM phase: pair shares rows 8p..8p+7; warp covers 8 col-pairs ----
    int og = ((warp & 1) << 3) | (lane & 7);   // col pair (og, og+16)
    int rq = lane >> 3;                        // row pair within the 8
    int R = pair * 8 + rq * 2;                 // rows R, R+1
    const float* zA = zsh + R * 160;
    const float* zB = zsh + (R + 1) * 160;

    ull aAlo = 0ull, aAhi = 0ull, aBlo = 0ull, aBhi = 0ull;
    #pragma unroll 4
    for (int it = 0; it < 40; it++) {
        ulonglong2 wv0 = WT4[(2 * it) * 16 + og];      // 8 distinct addrs: 1 wf
        ulonglong2 wv1 = WT4[(2 * it + 1) * 16 + og];
        ulonglong2 za = *(const ulonglong2*)(zA + it * 4);
        ulonglong2 zb = *(const ulonglong2*)(zB + it * 4);
        FMA2(aAlo, za.x, wv0.x);  FMA2(aAhi, za.x, wv0.y);
        FMA2(aAlo, za.y, wv1.x);  FMA2(aAhi, za.y, wv1.y);
        FMA2(aBlo, zb.x, wv0.x);  FMA2(aBhi, zb.x, wv0.y);
        FMA2(aBlo, zb.y, wv1.x);  FMA2(aBhi, zb.y, wv1.y);
    }

    union U { ull u; float2 f; } uv;
    float blo = biastot[og], bhi = biastot[og + 16];
    uv.u = aAlo; float LA = uv.f.x + uv.f.y + blo;
    uv.u = aAhi; float HA = fmaxf(uv.f.x + uv.f.y + bhi, 0.f);
    uv.u = aBlo; float LB = uv.f.x + uv.f.y + blo;
    uv.u = aBhi; float HB = fmaxf(uv.f.x + uv.f.y + bhi, 0.f);

    int rowA = row0 + R;
    outp[rowA * FF + og]            = LA;
    outp[rowA * FF + og + 16]       = HA;
    outp[(rowA + 1) * FF + og]      = LB;
    outp[(rowA + 1) * FF + og + 16] = HB;

    // BN stats: fold 2 rows in-thread, fold rq (lane bits 3,4), shared atomics.
    float slo = LA + LB,  sslo = LA * LA + LB * LB;
    float shi = HA + HB,  sshi = HA * HA + HB * HB;
    slo  += __shfl_xor_sync(0xffffffffu, slo, 8);
    sslo += __shfl_xor_sync(0xffffffffu, sslo, 8);
    shi  += __shfl_xor_sync(0xffffffffu, shi, 8);
    sshi += __shfl_xor_sync(0xffffffffu, sshi, 8);
    slo  += __shfl_xor_sync(0xffffffffu, slo, 16);
    sslo += __shfl_xor_sync(0xffffffffu, sslo, 16);
    shi  += __shfl_xor_sync(0xffffffffu, shi, 16);
    sshi += __shfl_xor_sync(0xffffffffu, sshi, 16);
    if (lane < 8) {
        atomicAdd(&s_sum[og],      slo);
        atomicAdd(&s_ssq[og],      sslo);
        atomicAdd(&s_sum[og + 16], shi);
        atomicAdd(&s_ssq[og + 16], sshi);
    }
    __syncthreads();
    if (tid < 32) {
        atomicAdd(&stats[tid],      s_sum[tid]);
        atomicAdd(&stats[32 + tid], s_ssq[tid]);
    }
}

// ---------------------------------------------------------------------------
__global__ void k_norm(float* __restrict__ out,
                       const float* __restrict__ bnxw, const float* __restrict__ bnxb,
                       const float* __restrict__ bnyw, const float* __restrict__ bnyb)
{
    int i = blockIdx.x * 256 + threadIdx.x;       // [0, (NN+EE)*8), exact
    int c0 = (i & 7) * 4;
    bool isx = i < NN * 8;
    int base = isx ? 0 : 64;
    float cnt = isx ? (float)NN : (float)EE;
    const float* wv = isx ? bnxw : bnyw;
    const float* bv = isx ? bnxb : bnyb;
    float4 v = ((float4*)out)[i];
    float* vp = (float*)&v;
    #pragma unroll
    for (int k = 0; k < 4; k++) {
        int c = c0 + k;
        float mean = g_stats[base + c] / cnt;
        float var  = g_stats[base + 32 + c] / cnt - mean * mean;
        vp[k] = (vp[k] - mean) * rsqrtf(var + EPS) * wv[c] + bv[c];
    }
    ((float4*)out)[i] = v;
}

// ---------------------------------------------------------------------------
extern "C" void kernel_launch(void* const* d_in, const int* in_sizes, int n_in,
                              void* d_out, int out_size)
{
    const float* x        = (const float*)d_in[0];
    const float* y        = (const float*)d_in[1];
    const float* deg_g    = (const float*)d_in[2];
    const float* deg_lg   = (const float*)d_in[3];
    const int*   t_g      = (const int*)d_in[4];
    const int*   tt_g     = (const int*)d_in[5];
    const int*   t_lg     = (const int*)d_in[6];
    const int*   tt_lg    = (const int*)d_in[7];
    const int*   dst      = (const int*)d_in[8];
    const int*   pm_pd    = (const int*)d_in[9];
    const float* theta_x_w   = (const float*)d_in[10];
    const float* theta_x_b   = (const float*)d_in[11];
    const float* theta_deg_w = (const float*)d_in[12];
    const float* theta_deg_b = (const float*)d_in[13];
    const float* theta_y_w   = (const float*)d_in[14];
    const float* theta_y_b   = (const float*)d_in[15];
    const float* gamma_y_w   = (const float*)d_in[16];
    const float* gamma_y_b   = (const float*)d_in[17];
    const float* gamma_deg_w = (const float*)d_in[18];
    const float* gamma_deg_b = (const float*)d_in[19];
    const float* gamma_x_w   = (const float*)d_in[20];
    const float* gamma_x_b   = (const float*)d_in[21];
    const float* theta_r_w   = (const float*)d_in[22];  // [2,32,32]
    const float* theta_r_b   = (const float*)d_in[23];  // [2,32]
    const float* gamma_r_w   = (const float*)d_in[24];
    const float* gamma_r_b   = (const float*)d_in[25];
    const float* bn_x_w      = (const float*)d_in[26];
    const float* bn_x_b      = (const float*)d_in[27];
    const float* bn_y_w      = (const float*)d_in[28];
    const float* bn_y_b      = (const float*)d_in[29];
    float* out = (float*)d_out;

    cudaFuncSetAttribute(k_main, cudaFuncAttributeMaxDynamicSharedMemorySize,
                         SMEM_BYTES);

    k_zero<<<NN * 8 / 256, 256>>>();
    k_scatter<<<EE * 16 / 256, 256>>>(y, dst);

    // Node side: z = [x, deg*x, agg_t, agg_tt, pmpd_y]
    k_main<<<NN / RPB, 256, SMEM_BYTES>>>(
        x, deg_g, t_g, tt_g, /*psrc=*/nullptr, /*pidx=*/nullptr,
        theta_x_w, theta_deg_w, theta_r_w, theta_r_w + 1024, theta_y_w,
        theta_x_b, theta_deg_b, theta_r_b, theta_r_b + 32, theta_y_b,
        out, /*statoff=*/0);

    // Edge side: z = [y, deg*y, agg_t, agg_tt, x[pm_pd]]
    k_main<<<EE / RPB, 256, SMEM_BYTES>>>(
        y, deg_lg, t_lg, tt_lg, /*psrc=*/x, /*pidx=*/pm_pd,
        gamma_y_w, gamma_deg_w, gamma_r_w, gamma_r_w + 1024, gamma_x_w,
        gamma_y_b, gamma_deg_b, gamma_r_b, gamma_r_b + 32, gamma_x_b,
        out + NN * FF, /*statoff=*/64);

    k_norm<<<(NN + EE) * 8 / 256, 256>>>(out, bn_x_w, bn_x_b, bn_y_w, bn_y_b);
}

// round 15
// speedup vs baseline: 1.3198x; 1.1353x over previous
#include <cuda_runtime.h>

#define NN 100000
#define EE 200000
#define KK 16
#define FF 32
#define EPS 1e-5f
#define RPB 32      // rows per block (NN, EE both divide exactly)
#define SMEM_BYTES (RPB*160*4 + 80*16*16)   // zsh 20480 + WT4 20480 = 40960

typedef unsigned long long ull;

// Scratch (static device globals — no allocation).
__device__ float g_pmpd[NN * FF];   // segment_sum(y, dst) -> [N, F]
__device__ float g_stats[128];      // [xsum32 | xssq32 | ysum32 | yssq32]

#define FMA2(acc, a, b) asm("fma.rn.f32x2 %0, %1, %2, %0;" : "+l"(acc) : "l"(a), "l"(b))
#define FADD2(acc, a)   asm("add.rn.f32x2 %0, %0, %1;"     : "+l"(acc) : "l"(a))

// ---------------------------------------------------------------------------
__global__ void k_zero() {
    int i = blockIdx.x * 256 + threadIdx.x;      // [0, NN*8)
    ((float4*)g_pmpd)[i] = make_float4(0.f, 0.f, 0.f, 0.f);
    if (i < 128) g_stats[i] = 0.f;
}

// segment_sum: vectorized f32x2 global reductions (red.global.add.v2.f32).
// 3.2M 8-byte REDGs (half the scalar count); proven correct in R9/R10/R11.
__global__ void k_scatter(const float* __restrict__ y, const int* __restrict__ dst) {
    int i = blockIdx.x * 256 + threadIdx.x;   // [0, EE*16), exact
    int e = i >> 4, c = i & 15;               // 16 float2 chunks per 32-f row
    int d = __ldg(&dst[e]);
    float2 v = ((const float2*)y)[i];
    float* p = g_pmpd + d * FF + c * 2;
    asm volatile("{\n\t.reg .u64 q;\n\tcvta.to.global.u64 q, %0;\n\t"
                 "red.global.add.v2.f32 [q], {%1, %2};\n\t}"
                 :: "l"(p), "f"(v.x), "f"(v.y) : "memory");
}

// ---------------------------------------------------------------------------
// Fused per-row kernel — byte-identical to the R8 champion (273.2us config).
// Row z = [v, deg*v, sum_t, sum_tt, p] (160 floats),
// out = z @ Wbig + bias ; relu cols [16:32) ; BN stats accumulation.
// 256 threads = 8 warps = 32 rows/block (5 blocks/SM, 62.5% occ).
//   Gather: LDG.64 two-neighbor-rows-per-instruction, fold via shfl.xor(16).
//   GEMM:   warp-autonomous — thread (g=lane>>4, o=lane&15) does 2 rows x
//           col-pair (o, o+16), j-packed fma.rn.f32x2.
// ---------------------------------------------------------------------------
__global__ __launch_bounds__(256, 5) void k_main(
    const float* __restrict__ feat, const float* __restrict__ deg,
    const int* __restrict__ t, const int* __restrict__ tt,
    const float* __restrict__ psrc, const int* __restrict__ pidx,
    const float* __restrict__ w0, const float* __restrict__ w1,
    const float* __restrict__ w2, const float* __restrict__ w3,
    const float* __restrict__ w4,
    const float* __restrict__ b0, const float* __restrict__ b1,
    const float* __restrict__ b2, const float* __restrict__ b3,
    const float* __restrict__ b4,
    float* __restrict__ outp, int statoff)
{
    extern __shared__ char smem[];
    float* zsh = (float*)smem;                          // [RPB][160]
    float4* WT4s = (float4*)(smem + RPB * 160 * 4);     // [80][16] staging view
    const ulonglong2* WT4 = (const ulonglong2*)WT4s;    // read view
    __shared__ float biastot[32];
    __shared__ float s_sum[32], s_ssq[32];

    const float* pbase = psrc ? psrc : g_pmpd;
    float* stats = g_stats + statoff;

    int tid = threadIdx.x;
    // Stage packed weights: WT4[j2*16+o] = {W[2j2][o], W[2j2+1][o],
    //                                       W[2j2][o+16], W[2j2+1][o+16]}
    for (int i = tid; i < 80 * 16; i += 256) {
        int j2 = i >> 4, o = i & 15;
        int j = 2 * j2;
        const float* src = (j < 32) ? w0 : (j < 64) ? w1 : (j < 96) ? w2
                                   : (j < 128) ? w3 : w4;
        int jr = j & 31;
        WT4s[i] = make_float4(src[jr * 32 + o],        src[(jr + 1) * 32 + o],
                              src[jr * 32 + o + 16],   src[(jr + 1) * 32 + o + 16]);
    }
    if (tid < 32) {
        biastot[tid] = b0[tid] + b1[tid] + b2[tid] + b3[tid] + b4[tid];
        s_sum[tid] = 0.f; s_ssq[tid] = 0.f;
    }
    __syncthreads();

    int lane = tid & 31, warp = tid >> 5;
    int row0 = blockIdx.x * RPB;
    int rbase = warp * 4;                 // 4 rows per warp
    int l4 = lane & 15;                   // float2 chunk within a 128B row
    int hb = lane >> 4;                   // which of the 2 rows this instr fetches
    const ull* fb = (const ull*)feat;     // feat as float2 (8B) elements

    // ---- Gather phase: 2 interleaved rows at a time ----
    #pragma unroll
    for (int s = 0; s < 4; s += 2) {
        int m0 = rbase + s, m1 = m0 + 1;
        int n0 = row0 + m0, n1 = row0 + m1;
        float xv0 = feat[n0 * FF + lane];
        float xv1 = feat[n1 * FF + lane];
        float dv0 = deg[n0] * xv0;
        float dv1 = deg[n1] * xv1;
        int ir0 = (lane < 16) ? t[n0 * KK + lane] : tt[n0 * KK + lane - 16];
        int ir1 = (lane < 16) ? t[n1 * KK + lane] : tt[n1 * KK + lane - 16];

        ull a00 = 0ull, a01 = 0ull, a10 = 0ull, a11 = 0ull;
        #pragma unroll
        for (int q = 0; q < 8; q++) {
            int sl = 2 * q + hb;
            int i00 = __shfl_sync(0xffffffffu, ir0, sl);
            int i01 = __shfl_sync(0xffffffffu, ir0, sl + 16);
            int i10 = __shfl_sync(0xffffffffu, ir1, sl);
            int i11 = __shfl_sync(0xffffffffu, ir1, sl + 16);
            ull v00 = fb[i00 * 16 + l4];
            ull v01 = fb[i01 * 16 + l4];
            ull v10 = fb[i10 * 16 + l4];
            ull v11 = fb[i11 * 16 + l4];
            FADD2(a00, v00);
            FADD2(a01, v01);
            FADD2(a10, v10);
            FADD2(a11, v11);
        }
        ull f00 = __shfl_xor_sync(0xffffffffu, a00, 16); FADD2(a00, f00);
        ull f01 = __shfl_xor_sync(0xffffffffu, a01, 16); FADD2(a01, f01);
        ull f10 = __shfl_xor_sync(0xffffffffu, a10, 16); FADD2(a10, f10);
        ull f11 = __shfl_xor_sync(0xffffffffu, a11, 16); FADD2(a11, f11);

        float pv0 = pidx ? pbase[pidx[n0] * FF + lane] : pbase[n0 * FF + lane];
        float pv1 = pidx ? pbase[pidx[n1] * FF + lane] : pbase[n1 * FF + lane];
        float* zr0 = zsh + m0 * 160;
        float* zr1 = zsh + m1 * 160;
        zr0[lane] = xv0;       zr1[lane] = xv1;
        zr0[32 + lane] = dv0;  zr1[32 + lane] = dv1;
        union Uc { ull u; float2 f; } c0, c1;
        c0.u = hb ? a01 : a00;
        c1.u = hb ? a11 : a10;
        int zo = (hb ? 96 : 64) + 2 * l4;
        *(float2*)(zr0 + zo) = c0.f;
        *(float2*)(zr1 + zo) = c1.f;
        zr0[128 + lane] = pv0; zr1[128 + lane] = pv1;
    }
    __syncwarp();   // z produced & consumed within the same warp only

    // ---- GEMM phase: thread = 2 rows x col-pair, j-packed f32x2 ----
    int g = hb, o = l4;
    int mA = rbase + g * 2;               // rows mA, mA+1
    const float* zA = zsh + mA * 160;
    const float* zB = zsh + (mA + 1) * 160;

    ull accAlo = 0ull, accAhi = 0ull, accBlo = 0ull, accBhi = 0ull;
    #pragma unroll 4
    for (int j2 = 0; j2 < 80; j2 += 2) {
        ulonglong2 za = *(const ulonglong2*)(zA + j2 * 2);
        ulonglong2 zb = *(const ulonglong2*)(zB + j2 * 2);
        ulonglong2 wv0 = WT4[j2 * 16 + o];        // .x = lo-col pair, .y = hi-col pair
        ulonglong2 wv1 = WT4[(j2 + 1) * 16 + o];
        FMA2(accAlo, za.x, wv0.x);  FMA2(accAhi, za.x, wv0.y);
        FMA2(accAlo, za.y, wv1.x);  FMA2(accAhi, za.y, wv1.y);
        FMA2(accBlo, zb.x, wv0.x);  FMA2(accBhi, zb.x, wv0.y);
        FMA2(accBlo, zb.y, wv1.x);  FMA2(accBhi, zb.y, wv1.y);
    }

    union U { ull u; float2 f; } uAlo, uAhi, uBlo, uBhi;
    uAlo.u = accAlo; uAhi.u = accAhi; uBlo.u = accBlo; uBhi.u = accBhi;
    float blo = biastot[o], bhi = biastot[o + 16];

    float loA = uAlo.f.x + uAlo.f.y + blo;
    float hiA = fmaxf(uAhi.f.x + uAhi.f.y + bhi, 0.f);
    float loB = uBlo.f.x + uBlo.f.y + blo;
    float hiB = fmaxf(uBhi.f.x + uBhi.f.y + bhi, 0.f);

    int rA = row0 + mA;
    outp[rA * FF + o]            = loA;
    outp[rA * FF + o + 16]       = hiA;
    outp[(rA + 1) * FF + o]      = loB;
    outp[(rA + 1) * FF + o + 16] = hiB;

    // BN stats: fold 2 rows in-thread, fold g0/g1 via shuffle, shared atomics.
    float slo = loA + loB,        sslo = loA * loA + loB * loB;
    float shi = hiA + hiB,        sshi = hiA * hiA + hiB * hiB;
    slo  += __shfl_xor_sync(0xffffffffu, slo, 16);
    sslo += __shfl_xor_sync(0xffffffffu, sslo, 16);
    shi  += __shfl_xor_sync(0xffffffffu, shi, 16);
    sshi += __shfl_xor_sync(0xffffffffu, sshi, 16);
    if (lane < 16) {
        atomicAdd(&s_sum[o],      slo);
        atomicAdd(&s_ssq[o],      sslo);
        atomicAdd(&s_sum[o + 16], shi);
        atomicAdd(&s_ssq[o + 16], sshi);
    }
    __syncthreads();
    if (tid < 32) {
        atomicAdd(&stats[tid],      s_sum[tid]);
        atomicAdd(&stats[32 + tid], s_ssq[tid]);
    }
}

// ---------------------------------------------------------------------------
__global__ void k_norm(float* __restrict__ out,
                       const float* __restrict__ bnxw, const float* __restrict__ bnxb,
                       const float* __restrict__ bnyw, const float* __restrict__ bnyb)
{
    int i = blockIdx.x * 256 + threadIdx.x;       // [0, (NN+EE)*8), exact
    int c0 = (i & 7) * 4;
    bool isx = i < NN * 8;
    int base = isx ? 0 : 64;
    float cnt = isx ? (float)NN : (float)EE;
    const float* wv = isx ? bnxw : bnyw;
    const float* bv = isx ? bnxb : bnyb;
    float4 v = ((float4*)out)[i];
    float* vp = (float*)&v;
    #pragma unroll
    for (int k = 0; k < 4; k++) {
        int c = c0 + k;
        float mean = g_stats[base + c] / cnt;
        float var  = g_stats[base + 32 + c] / cnt - mean * mean;
        vp[k] = (vp[k] - mean) * rsqrtf(var + EPS) * wv[c] + bv[c];
    }
    ((float4*)out)[i] = v;
}

// ---------------------------------------------------------------------------
extern "C" void kernel_launch(void* const* d_in, const int* in_sizes, int n_in,
                              void* d_out, int out_size)
{
    const float* x        = (const float*)d_in[0];
    const float* y        = (const float*)d_in[1];
    const float* deg_g    = (const float*)d_in[2];
    const float* deg_lg   = (const float*)d_in[3];
    const int*   t_g      = (const int*)d_in[4];
    const int*   tt_g     = (const int*)d_in[5];
    const int*   t_lg     = (const int*)d_in[6];
    const int*   tt_lg    = (const int*)d_in[7];
    const int*   dst      = (const int*)d_in[8];
    const int*   pm_pd    = (const int*)d_in[9];
    const float* theta_x_w   = (const float*)d_in[10];
    const float* theta_x_b   = (const float*)d_in[11];
    const float* theta_deg_w = (const float*)d_in[12];
    const float* theta_deg_b = (const float*)d_in[13];
    const float* theta_y_w   = (const float*)d_in[14];
    const float* theta_y_b   = (const float*)d_in[15];
    const float* gamma_y_w   = (const float*)d_in[16];
    const float* gamma_y_b   = (const float*)d_in[17];
    const float* gamma_deg_w = (const float*)d_in[18];
    const float* gamma_deg_b = (const float*)d_in[19];
    const float* gamma_x_w   = (const float*)d_in[20];
    const float* gamma_x_b   = (const float*)d_in[21];
    const float* theta_r_w   = (const float*)d_in[22];  // [2,32,32]
    const float* theta_r_b   = (const float*)d_in[23];  // [2,32]
    const float* gamma_r_w   = (const float*)d_in[24];
    const float* gamma_r_b   = (const float*)d_in[25];
    const float* bn_x_w      = (const float*)d_in[26];
    const float* bn_x_b      = (const float*)d_in[27];
    const float* bn_y_w      = (const float*)d_in[28];
    const float* bn_y_b      = (const float*)d_in[29];
    float* out = (float*)d_out;

    cudaFuncSetAttribute(k_main, cudaFuncAttributeMaxDynamicSharedMemorySize,
                         SMEM_BYTES);

    k_zero<<<NN * 8 / 256, 256>>>();
    k_scatter<<<EE * 16 / 256, 256>>>(y, dst);

    // Node side: z = [x, deg*x, agg_t, agg_tt, pmpd_y]
    k_main<<<NN / RPB, 256, SMEM_BYTES>>>(
        x, deg_g, t_g, tt_g, /*psrc=*/nullptr, /*pidx=*/nullptr,
        theta_x_w, theta_deg_w, theta_r_w, theta_r_w + 1024, theta_y_w,
        theta_x_b, theta_deg_b, theta_r_b, theta_r_b + 32, theta_y_b,
        out, /*statoff=*/0);

    // Edge side: z = [y, deg*y, agg_t, agg_tt, x[pm_pd]]
    k_main<<<EE / RPB, 256, SMEM_BYTES>>>(
        y, deg_lg, t_lg, tt_lg, /*psrc=*/x, /*pidx=*/pm_pd,
        gamma_y_w, gamma_deg_w, gamma_r_w, gamma_r_w + 1024, gamma_x_w,
        gamma_y_b, gamma_deg_b, gamma_r_b, gamma_r_b + 32, gamma_x_b,
        out + NN * FF, /*statoff=*/64);

    k_norm<<<(NN + EE) * 8 / 256, 256>>>(out, bn_x_w, bn_x_b, bn_y_w, bn_y_b);
}

// round 17
// speedup vs baseline: 1.4698x; 1.1137x over previous
#include <cuda_runtime.h>
#include <cuda_fp16.h>
#include <cstdint>

#define NN 100000
#define EE 200000
#define KK 16
#define FF 32
#define EPS 1e-5f
#define RPB 32
#define ZST 168                    // halfs per row: 336B = 21*16B, 16B-aligned
#define WHALF (32*ZST)             // 5376 halfs per W image

typedef unsigned long long ull;

__device__ float g_pmpd[NN * FF];
__device__ float g_stats[128];     // [xsum|xssq|ysum|yssq]
__device__ float g_btot[64];
__device__ __align__(16) __half g_Wimg[2][2][WHALF];  // [side][hi/res][n*ZST+k]

#define FADD2(acc, a) asm("add.rn.f32x2 %0, %0, %1;" : "+l"(acc) : "l"(a))

__device__ __forceinline__ uint32_t smem_u32(const void* p) {
    uint32_t a;
    asm("{ .reg .u64 t; cvta.to.shared.u64 t, %1; cvt.u32.u64 %0, t; }" : "=r"(a) : "l"(p));
    return a;
}

// ---------------------------------------------------------------------------
__global__ void k_zero() {
    int i = blockIdx.x * 256 + threadIdx.x;      // [0, NN*8)
    ((float4*)g_pmpd)[i] = make_float4(0.f, 0.f, 0.f, 0.f);
    if (i < 128) g_stats[i] = 0.f;
}

// Pre-pack W as fp16 hi + fp16 residual, [n=32][k=0..159] row-major, stride ZST.
__global__ void k_prepw(
    const float* txw, const float* tdw, const float* trw, const float* tyw,
    const float* gyw, const float* gdw, const float* grw, const float* gxw,
    const float* txb, const float* tdb, const float* trb, const float* tyb,
    const float* gyb, const float* gdb, const float* grb, const float* gxb)
{
    int tid = threadIdx.x;
    if (tid < 64) {
        int side = tid >> 5, c = tid & 31;
        g_btot[tid] = side ? (gyb[c] + gdb[c] + grb[c] + grb[32 + c] + gxb[c])
                           : (txb[c] + tdb[c] + trb[c] + trb[32 + c] + tyb[c]);
    }
    for (int i = tid; i < 2 * 32 * 160; i += 256) {
        int side = i / 5120, r = i % 5120;
        int o = r / 160, j = r % 160;
        int seg = j >> 5, jr = j & 31;
        const float* src;
        if (side == 0)
            src = (seg == 0) ? txw : (seg == 1) ? tdw : (seg == 2) ? trw
                : (seg == 3) ? trw + 1024 : tyw;
        else
            src = (seg == 0) ? gyw : (seg == 1) ? gdw : (seg == 2) ? grw
                : (seg == 3) ? grw + 1024 : gxw;
        float v = src[jr * 32 + o];
        __half h1 = __float2half_rn(v);
        __half h2 = __float2half_rn(v - __half2float(h1));
        g_Wimg[side][0][o * ZST + j] = h1;
        g_Wimg[side][1][o * ZST + j] = h2;
    }
}

// segment_sum: vectorized f32x2 global reductions (proven).
__global__ void k_scatter(const float* __restrict__ y, const int* __restrict__ dst) {
    int i = blockIdx.x * 256 + threadIdx.x;   // [0, EE*16), exact
    int e = i >> 4, c = i & 15;
    int d = __ldg(&dst[e]);
    float2 v = ((const float2*)y)[i];
    float* p = g_pmpd + d * FF + c * 2;
    asm volatile("{\n\t.reg .u64 q;\n\tcvta.to.global.u64 q, %0;\n\t"
                 "red.global.add.v2.f32 [q], {%1, %2};\n\t}"
                 :: "l"(p), "f"(v.x), "f"(v.y) : "memory");
}

// ---------------------------------------------------------------------------
// Gather (champion R8 loop, fp16 z) + HMMA GEMM (m16n8k16, W hi+residual).
// 8 warps: gather 4 rows each; GEMM warp = (mt = warp>>2, nb = (warp&3)*8).
// ---------------------------------------------------------------------------
__global__ __launch_bounds__(256) void k_main(
    const float* __restrict__ feat, const float* __restrict__ deg,
    const int* __restrict__ t, const int* __restrict__ tt,
    const float* __restrict__ psrc, const int* __restrict__ pidx,
    float* __restrict__ outp, int side)
{
    __shared__ __align__(16) __half sZ[RPB * ZST];       // 10752 B
    __shared__ __align__(16) __half sW[2][WHALF];        // 21504 B (hi, res)
    __shared__ float sb[32], s_sum[32], s_ssq[32];

    int tid = threadIdx.x, lane = tid & 31, warp = tid >> 5;
    if (tid < 32) { sb[tid] = g_btot[side * 32 + tid]; s_sum[tid] = 0.f; s_ssq[tid] = 0.f; }
    {   // copy both W images: 21504 B
        const uint4* s = (const uint4*)g_Wimg[side];
        uint4* d = (uint4*)sW;
        for (int i = tid; i < 1344; i += 256) d[i] = s[i];
    }

    const float* pbase = psrc ? psrc : g_pmpd;
    int row0 = blockIdx.x * RPB;
    int rbase = warp * 4;
    int l4 = lane & 15, hb = lane >> 4;
    const ull* fb = (const ull*)feat;

    // ---- Gather phase (champion): 2 interleaved rows at a time, f16 out ----
    #pragma unroll
    for (int s = 0; s < 4; s += 2) {
        int m0 = rbase + s, m1 = m0 + 1;
        int n0 = row0 + m0, n1 = row0 + m1;
        float xv0 = feat[n0 * FF + lane];
        float xv1 = feat[n1 * FF + lane];
        float dv0 = deg[n0] * xv0;
        float dv1 = deg[n1] * xv1;
        int ir0 = (lane < 16) ? t[n0 * KK + lane] : tt[n0 * KK + lane - 16];
        int ir1 = (lane < 16) ? t[n1 * KK + lane] : tt[n1 * KK + lane - 16];

        ull a00 = 0ull, a01 = 0ull, a10 = 0ull, a11 = 0ull;
        #pragma unroll
        for (int q = 0; q < 8; q++) {
            int sl = 2 * q + hb;
            int i00 = __shfl_sync(0xffffffffu, ir0, sl);
            int i01 = __shfl_sync(0xffffffffu, ir0, sl + 16);
            int i10 = __shfl_sync(0xffffffffu, ir1, sl);
            int i11 = __shfl_sync(0xffffffffu, ir1, sl + 16);
            ull v00 = fb[i00 * 16 + l4];
            ull v01 = fb[i01 * 16 + l4];
            ull v10 = fb[i10 * 16 + l4];
            ull v11 = fb[i11 * 16 + l4];
            FADD2(a00, v00); FADD2(a01, v01); FADD2(a10, v10); FADD2(a11, v11);
        }
        ull f00 = __shfl_xor_sync(0xffffffffu, a00, 16); FADD2(a00, f00);
        ull f01 = __shfl_xor_sync(0xffffffffu, a01, 16); FADD2(a01, f01);
        ull f10 = __shfl_xor_sync(0xffffffffu, a10, 16); FADD2(a10, f10);
        ull f11 = __shfl_xor_sync(0xffffffffu, a11, 16); FADD2(a11, f11);

        float pv0 = pidx ? pbase[pidx[n0] * FF + lane] : pbase[n0 * FF + lane];
        float pv1 = pidx ? pbase[pidx[n1] * FF + lane] : pbase[n1 * FF + lane];
        __half* hz0 = sZ + m0 * ZST;
        __half* hz1 = sZ + m1 * ZST;
        hz0[lane]       = __float2half_rn(xv0);
        hz1[lane]       = __float2half_rn(xv1);
        hz0[32 + lane]  = __float2half_rn(dv0);
        hz1[32 + lane]  = __float2half_rn(dv1);
        union Uc { ull u; float2 f; } c0, c1;
        c0.u = hb ? a01 : a00;
        c1.u = hb ? a11 : a10;
        int zo = (hb ? 96 : 64) + 2 * l4;
        *(__half2*)(hz0 + zo) = __floats2half2_rn(c0.f.x, c0.f.y);
        *(__half2*)(hz1 + zo) = __floats2half2_rn(c1.f.x, c1.f.y);
        hz0[128 + lane] = __float2half_rn(pv0);
        hz1[128 + lane] = __float2half_rn(pv1);
    }
    __syncthreads();

    // ---- HMMA GEMM: warp computes rows [mt*16, +16) x cols [nb, nb+8) ----
    int mt = warp >> 2, nb = (warp & 3) * 8;
    int gid = lane >> 2, tig = lane & 3;
    uint32_t zbase = smem_u32(sZ);
    uint32_t wbase = smem_u32(sW);
    int arow = mt * 16 + (lane & 15);
    int akoff = (lane & 16) ? 8 : 0;
    int bn = nb + (lane & 7);
    int bkoff = (lane & 8) ? 8 : 0;

    float d0 = 0.f, d1 = 0.f, d2 = 0.f, d3 = 0.f;
    #pragma unroll
    for (int k0 = 0; k0 < 160; k0 += 16) {
        uint32_t aaddr = zbase + (uint32_t)(arow * ZST + k0 + akoff) * 2u;
        uint32_t a0, a1, a2, a3;
        asm volatile("ldmatrix.sync.aligned.m8n8.x4.shared.b16 {%0,%1,%2,%3}, [%4];"
                     : "=r"(a0), "=r"(a1), "=r"(a2), "=r"(a3) : "r"(aaddr));
        uint32_t bh = wbase + (uint32_t)(bn * ZST + k0 + bkoff) * 2u;
        uint32_t b0, b1;
        asm volatile("ldmatrix.sync.aligned.m8n8.x2.shared.b16 {%0,%1}, [%2];"
                     : "=r"(b0), "=r"(b1) : "r"(bh));
        asm volatile("mma.sync.aligned.m16n8k16.row.col.f32.f16.f16.f32 "
                     "{%0,%1,%2,%3}, {%4,%5,%6,%7}, {%8,%9}, {%0,%1,%2,%3};"
                     : "+f"(d0), "+f"(d1), "+f"(d2), "+f"(d3)
                     : "r"(a0), "r"(a1), "r"(a2), "r"(a3), "r"(b0), "r"(b1));
        uint32_t br = bh + WHALF * 2u;        // residual image
        asm volatile("ldmatrix.sync.aligned.m8n8.x2.shared.b16 {%0,%1}, [%2];"
                     : "=r"(b0), "=r"(b1) : "r"(br));
        asm volatile("mma.sync.aligned.m16n8k16.row.col.f32.f16.f16.f32 "
                     "{%0,%1,%2,%3}, {%4,%5,%6,%7}, {%8,%9}, {%0,%1,%2,%3};"
                     : "+f"(d0), "+f"(d1), "+f"(d2), "+f"(d3)
                     : "r"(a0), "r"(a1), "r"(a2), "r"(a3), "r"(b0), "r"(b1));
    }

    // ---- Epilogue: bias, relu (cols>=16), store, BN stats ----
    int c0col = nb + 2 * tig;
    float b0f = sb[c0col], b1f = sb[c0col + 1];
    bool rel = (nb >= 16);
    float v00 = d0 + b0f, v01 = d1 + b1f;     // row gid
    float v10 = d2 + b0f, v11 = d3 + b1f;     // row gid+8
    if (rel) {
        v00 = fmaxf(v00, 0.f); v01 = fmaxf(v01, 0.f);
        v10 = fmaxf(v10, 0.f); v11 = fmaxf(v11, 0.f);
    }
    int r0 = row0 + mt * 16 + gid;
    *(float2*)(outp + (size_t)r0 * FF + c0col)       = make_float2(v00, v01);
    *(float2*)(outp + (size_t)(r0 + 8) * FF + c0col) = make_float2(v10, v11);

    atomicAdd(&s_sum[c0col],     v00 + v10);
    atomicAdd(&s_ssq[c0col],     v00 * v00 + v10 * v10);
    atomicAdd(&s_sum[c0col + 1], v01 + v11);
    atomicAdd(&s_ssq[c0col + 1], v01 * v01 + v11 * v11);
    __syncthreads();
    if (tid < 32) {
        atomicAdd(&g_stats[side * 64 + tid],      s_sum[tid]);
        atomicAdd(&g_stats[side * 64 + 32 + tid], s_ssq[tid]);
    }
}

// ---------------------------------------------------------------------------
__global__ void k_norm(float* __restrict__ out,
                       const float* __restrict__ bnxw, const float* __restrict__ bnxb,
                       const float* __restrict__ bnyw, const float* __restrict__ bnyb)
{
    int i = blockIdx.x * 256 + threadIdx.x;       // [0, (NN+EE)*8), exact
    int c0 = (i & 7) * 4;
    bool isx = i < NN * 8;
    int base = isx ? 0 : 64;
    float cnt = isx ? (float)NN : (float)EE;
    const float* wv = isx ? bnxw : bnyw;
    const float* bv = isx ? bnxb : bnyb;
    float4 v = ((float4*)out)[i];
    float* vp = (float*)&v;
    #pragma unroll
    for (int k = 0; k < 4; k++) {
        int c = c0 + k;
        float mean = g_stats[base + c] / cnt;
        float var  = g_stats[base + 32 + c] / cnt - mean * mean;
        vp[k] = (vp[k] - mean) * rsqrtf(var + EPS) * wv[c] + bv[c];
    }
    ((float4*)out)[i] = v;
}

// ---------------------------------------------------------------------------
extern "C" void kernel_launch(void* const* d_in, const int* in_sizes, int n_in,
                              void* d_out, int out_size)
{
    const float* x        = (const float*)d_in[0];
    const float* y        = (const float*)d_in[1];
    const float* deg_g    = (const float*)d_in[2];
    const float* deg_lg   = (const float*)d_in[3];
    const int*   t_g      = (const int*)d_in[4];
    const int*   tt_g     = (const int*)d_in[5];
    const int*   t_lg     = (const int*)d_in[6];
    const int*   tt_lg    = (const int*)d_in[7];
    const int*   dst      = (const int*)d_in[8];
    const int*   pm_pd    = (const int*)d_in[9];
    const float* theta_x_w   = (const float*)d_in[10];
    const float* theta_x_b   = (const float*)d_in[11];
    const float* theta_deg_w = (const float*)d_in[12];
    const float* theta_deg_b = (const float*)d_in[13];
    const float* theta_y_w   = (const float*)d_in[14];
    const float* theta_y_b   = (const float*)d_in[15];
    const float* gamma_y_w   = (const float*)d_in[16];
    const float* gamma_y_b   = (const float*)d_in[17];
    const float* gamma_deg_w = (const float*)d_in[18];
    const float* gamma_deg_b = (const float*)d_in[19];
    const float* gamma_x_w   = (const float*)d_in[20];
    const float* gamma_x_b   = (const float*)d_in[21];
    const float* theta_r_w   = (const float*)d_in[22];  // [2,32,32]
    const float* theta_r_b   = (const float*)d_in[23];  // [2,32]
    const float* gamma_r_w   = (const float*)d_in[24];
    const float* gamma_r_b   = (const float*)d_in[25];
    const float* bn_x_w      = (const float*)d_in[26];
    const float* bn_x_b      = (const float*)d_in[27];
    const float* bn_y_w      = (const float*)d_in[28];
    const float* bn_y_b      = (const float*)d_in[29];
    float* out = (float*)d_out;

    k_prepw<<<1, 256>>>(theta_x_w, theta_deg_w, theta_r_w, theta_y_w,
                        gamma_y_w, gamma_deg_w, gamma_r_w, gamma_x_w,
                        theta_x_b, theta_deg_b, theta_r_b, theta_y_b,
                        gamma_y_b, gamma_deg_b, gamma_r_b, gamma_x_b);
    k_zero<<<NN * 8 / 256, 256>>>();
    k_scatter<<<EE * 16 / 256, 256>>>(y, dst);

    // Node side: z = [x, deg*x, agg_t, agg_tt, pmpd_y]
    k_main<<<NN / RPB, 256>>>(x, deg_g, t_g, tt_g, nullptr, nullptr, out, 0);
    // Edge side: z = [y, deg*y, agg_t, agg_tt, x[pm_pd]]
    k_main<<<EE / RPB, 256>>>(y, deg_lg, t_lg, tt_lg, x, pm_pd, out + NN * FF, 1);

    k_norm<<<(NN + EE) * 8 / 256, 256>>>(out, bn_x_w, bn_x_b, bn_y_w, bn_y_b);
}